// round 1
// baseline (speedup 1.0000x reference)
#include <cuda_runtime.h>
#include <cuda_bf16.h>
#include <math.h>

// Problem constants
#define BB 4
#define TT 2048
#define DD 1024
#define HH 16
#define HD 64
#define FF 4096
#define MM (BB*TT)          // 8192 rows

// ---------------- scratch (single __device__ arena) ----------------
// h:    [MM,DD]            off 0          8,388,608
// qkv:  [MM,3DD]           off 8388608    25,165,824
// ctx:  [MM,DD]            off 33554432   8,388,608
// x1:   [MM,DD]            off 41943040   8,388,608
// h2:   [MM,DD]            off 50331648   8,388,608
// ff:   [MM,FF]            off 58720256   33,554,432
// Wqkv: [DD,3DD]           off 92274688   3,145,728
// bqkv: [3DD]              off 95420416   3,072
#define OFF_H     0
#define OFF_QKV   8388608
#define OFF_CTX   33554432
#define OFF_X1    41943040
#define OFF_H2    50331648
#define OFF_FF    58720256
#define OFF_WQKV  92274688
#define OFF_BQKV  95420416
#define SCRATCH_TOTAL 95423488

__device__ float d_scratch[SCRATCH_TOTAL];

// ---------------- pack QKV weights: [H,D,HD]x3 -> [D, 3*D] ----------------
__global__ void pack_qkv_kernel(const float* __restrict__ Wq, const float* __restrict__ Wk,
                                const float* __restrict__ Wv, const float* __restrict__ bq,
                                const float* __restrict__ bk, const float* __restrict__ bv,
                                float* __restrict__ Wqkv, float* __restrict__ bqkv) {
    int idx = blockIdx.x * blockDim.x + threadIdx.x;
    if (idx < 3 * DD) {
        int proj = idx / DD, c = idx % DD;
        const float* sb = (proj == 0) ? bq : ((proj == 1) ? bk : bv);
        bqkv[idx] = sb[c];
    }
    if (idx >= DD * 3 * DD) return;
    int d  = idx / (3 * DD);
    int cc = idx % (3 * DD);
    int proj = cc / DD;
    int c    = cc % DD;
    const float* W = (proj == 0) ? Wq : ((proj == 1) ? Wk : Wv);
    // W[h, d, k] with h = c>>6, k = c&63
    Wqkv[idx] = W[(c >> 6) * (DD * HD) + d * HD + (c & 63)];
}

// ---------------- LayerNorm: one block per row ----------------
__global__ __launch_bounds__(256)
void layernorm_kernel(const float* __restrict__ x, const float* __restrict__ g,
                      const float* __restrict__ bta, float* __restrict__ out) {
    __shared__ float red[16];
    int row = blockIdx.x;
    const float* xr = x + (size_t)row * DD;
    float v[4];
    float s = 0.f, s2 = 0.f;
#pragma unroll
    for (int i = 0; i < 4; i++) {
        v[i] = xr[threadIdx.x + i * 256];
        s += v[i];
        s2 += v[i] * v[i];
    }
#pragma unroll
    for (int o = 16; o > 0; o >>= 1) {
        s  += __shfl_xor_sync(0xffffffffu, s,  o);
        s2 += __shfl_xor_sync(0xffffffffu, s2, o);
    }
    int w = threadIdx.x >> 5;
    if ((threadIdx.x & 31) == 0) { red[w] = s; red[w + 8] = s2; }
    __syncthreads();
    s = 0.f; s2 = 0.f;
#pragma unroll
    for (int i = 0; i < 8; i++) { s += red[i]; s2 += red[i + 8]; }
    float mu  = s * (1.f / (float)DD);
    float var = s2 * (1.f / (float)DD) - mu * mu;
    float inv = rsqrtf(var + 1e-5f);
#pragma unroll
    for (int i = 0; i < 4; i++) {
        int c = threadIdx.x + i * 256;
        out[(size_t)row * DD + c] = (v[i] - mu) * inv * g[c] + bta[c];
    }
}

// ---------------- SGEMM: C[M,N] = A[M,K] * B[K,N] + bias (+res / GELU) ----------------
// BM=128, BN=128, BK=16, 256 threads, 8x8 per thread.
// EPI: 0 = bias, 1 = bias + residual, 2 = bias + exact GELU
template <int EPI>
__global__ __launch_bounds__(256)
void sgemm_kernel(const float* __restrict__ A, const float* __restrict__ B,
                  const float* __restrict__ bias, const float* __restrict__ res,
                  float* __restrict__ C, int M, int N, int K) {
    __shared__ float As[16][128];   // transposed: As[k][m]
    __shared__ float Bs[16][128];
    int tid = threadIdx.x;
    int tx = tid & 15, ty = tid >> 4;
    int bm = blockIdx.y * 128;
    int bn = blockIdx.x * 128;

    float acc[8][8];
#pragma unroll
    for (int i = 0; i < 8; i++)
#pragma unroll
        for (int j = 0; j < 8; j++) acc[i][j] = 0.f;

    for (int k0 = 0; k0 < K; k0 += 16) {
        // A tile: 128x16 -> 512 float4 loads
#pragma unroll
        for (int i = 0; i < 2; i++) {
            int l = tid + i * 256;
            int row = l >> 2;
            int cv = l & 3;
            float4 v = *(const float4*)(A + (size_t)(bm + row) * K + k0 + cv * 4);
            As[cv * 4 + 0][row] = v.x;
            As[cv * 4 + 1][row] = v.y;
            As[cv * 4 + 2][row] = v.z;
            As[cv * 4 + 3][row] = v.w;
        }
        // B tile: 16x128
#pragma unroll
        for (int i = 0; i < 2; i++) {
            int l = tid + i * 256;
            int row = l >> 5;
            int cv = l & 31;
            *(float4*)(&Bs[row][cv * 4]) =
                *(const float4*)(B + (size_t)(k0 + row) * N + bn + cv * 4);
        }
        __syncthreads();
#pragma unroll
        for (int kk = 0; kk < 16; kk++) {
            float a[8], b[8];
            *(float4*)(&a[0]) = *(const float4*)(&As[kk][ty * 8]);
            *(float4*)(&a[4]) = *(const float4*)(&As[kk][ty * 8 + 4]);
            *(float4*)(&b[0]) = *(const float4*)(&Bs[kk][tx * 8]);
            *(float4*)(&b[4]) = *(const float4*)(&Bs[kk][tx * 8 + 4]);
#pragma unroll
            for (int i = 0; i < 8; i++)
#pragma unroll
                for (int j = 0; j < 8; j++)
                    acc[i][j] = fmaf(a[i], b[j], acc[i][j]);
        }
        __syncthreads();
    }

#pragma unroll
    for (int i = 0; i < 8; i++) {
        int r = bm + ty * 8 + i;
#pragma unroll
        for (int j = 0; j < 8; j++) {
            int c = bn + tx * 8 + j;
            float v = acc[i][j] + bias[c];
            if (EPI == 1) v += res[(size_t)r * N + c];
            if (EPI == 2) v = 0.5f * v * (1.0f + erff(v * 0.70710678118654752f));
            C[(size_t)r * N + c] = v;
        }
    }
}

// ---------------- Flash attention (causal), fp32 ----------------
// grid: (T/64, H, B). 256 threads (16x16), 4x4 microtiles.
// qkv layout: [B*T, 3072] (Q at +0, K at +1024, V at +2048 per head chunk h*64).
// ctx out: [B, T, D] with head-concat layout (h*64 + k).
#define ATTN_SMEM (4 * 64 * 65 * 4)

__global__ __launch_bounds__(256)
void attn_kernel(const float* __restrict__ qkv, float* __restrict__ ctx) {
    extern __shared__ float sm[];
    float (*Qs)[65] = (float(*)[65])(sm);
    float (*Ks)[65] = (float(*)[65])(sm + 64 * 65);
    float (*Vs)[65] = (float(*)[65])(sm + 2 * 64 * 65);
    float (*Ps)[65] = (float(*)[65])(sm + 3 * 64 * 65);

    int qt = blockIdx.x, h = blockIdx.y, b = blockIdx.z;
    int tid = threadIdx.x;
    int tx = tid & 15, ty = tid >> 4;
    int q0 = qt * 64;

    // load Q (scaled by 1/sqrt(HD) = 0.125)
#pragma unroll
    for (int i = 0; i < 4; i++) {
        int l = tid + i * 256;      // float4 index, 0..1023
        int r = l >> 4;
        int c4 = (l & 15) * 4;
        float4 v = *(const float4*)(qkv + (size_t)(b * TT + q0 + r) * 3072 + h * 64 + c4);
        Qs[r][c4 + 0] = v.x * 0.125f;
        Qs[r][c4 + 1] = v.y * 0.125f;
        Qs[r][c4 + 2] = v.z * 0.125f;
        Qs[r][c4 + 3] = v.w * 0.125f;
    }

    float m[4], l[4], O[4][4];
#pragma unroll
    for (int i = 0; i < 4; i++) {
        m[i] = -1e30f; l[i] = 0.f;
#pragma unroll
        for (int j = 0; j < 4; j++) O[i][j] = 0.f;
    }

    for (int jt = 0; jt <= qt; jt++) {
        int kv0 = jt * 64;
        __syncthreads();   // protect K/V/P reuse (also covers Q stores on first iter)
#pragma unroll
        for (int i = 0; i < 4; i++) {
            int li = tid + i * 256;
            int r = li >> 4;
            int c4 = (li & 15) * 4;
            const float* base = qkv + (size_t)(b * TT + kv0 + r) * 3072 + h * 64;
            float4 kv4 = *(const float4*)(base + 1024 + c4);
            Ks[r][c4 + 0] = kv4.x; Ks[r][c4 + 1] = kv4.y;
            Ks[r][c4 + 2] = kv4.z; Ks[r][c4 + 3] = kv4.w;
            float4 vv4 = *(const float4*)(base + 2048 + c4);
            Vs[r][c4 + 0] = vv4.x; Vs[r][c4 + 1] = vv4.y;
            Vs[r][c4 + 2] = vv4.z; Vs[r][c4 + 3] = vv4.w;
        }
        __syncthreads();

        // S = Q K^T (thread owns rows ty*4.., cols tx*4..)
        float s[4][4];
#pragma unroll
        for (int i = 0; i < 4; i++)
#pragma unroll
            for (int j = 0; j < 4; j++) s[i][j] = 0.f;
#pragma unroll 8
        for (int k = 0; k < 64; k++) {
            float a[4], bb[4];
#pragma unroll
            for (int i = 0; i < 4; i++) a[i] = Qs[ty * 4 + i][k];
#pragma unroll
            for (int j = 0; j < 4; j++) bb[j] = Ks[tx * 4 + j][k];
#pragma unroll
            for (int i = 0; i < 4; i++)
#pragma unroll
                for (int j = 0; j < 4; j++)
                    s[i][j] = fmaf(a[i], bb[j], s[i][j]);
        }

        // causal mask (only needed on the diagonal tile)
        if (jt == qt) {
#pragma unroll
            for (int i = 0; i < 4; i++)
#pragma unroll
                for (int j = 0; j < 4; j++)
                    if (kv0 + tx * 4 + j > q0 + ty * 4 + i) s[i][j] = -1e30f;
        }

        // online softmax per row (reduce across the 16 tx lanes)
#pragma unroll
        for (int i = 0; i < 4; i++) {
            float mx = s[i][0];
#pragma unroll
            for (int j = 1; j < 4; j++) mx = fmaxf(mx, s[i][j]);
#pragma unroll
            for (int o = 8; o > 0; o >>= 1)
                mx = fmaxf(mx, __shfl_xor_sync(0xffffffffu, mx, o));
            float mnew = fmaxf(m[i], mx);
            float sc = __expf(m[i] - mnew);
            float sum = 0.f;
#pragma unroll
            for (int j = 0; j < 4; j++) {
                s[i][j] = __expf(s[i][j] - mnew);
                sum += s[i][j];
            }
#pragma unroll
            for (int o = 8; o > 0; o >>= 1)
                sum += __shfl_xor_sync(0xffffffffu, sum, o);
            l[i] = l[i] * sc + sum;
            m[i] = mnew;
#pragma unroll
            for (int j = 0; j < 4; j++) O[i][j] *= sc;
        }

        // stage P
#pragma unroll
        for (int i = 0; i < 4; i++)
#pragma unroll
            for (int j = 0; j < 4; j++)
                Ps[ty * 4 + i][tx * 4 + j] = s[i][j];
        __syncthreads();

        // O += P V
#pragma unroll 8
        for (int k = 0; k < 64; k++) {
            float p[4], vv[4];
#pragma unroll
            for (int i = 0; i < 4; i++) p[i] = Ps[ty * 4 + i][k];
#pragma unroll
            for (int j = 0; j < 4; j++) vv[j] = Vs[k][tx * 4 + j];
#pragma unroll
            for (int i = 0; i < 4; i++)
#pragma unroll
                for (int j = 0; j < 4; j++)
                    O[i][j] = fmaf(p[i], vv[j], O[i][j]);
        }
    }

    // write ctx with head-concat layout
#pragma unroll
    for (int i = 0; i < 4; i++) {
        float inv = 1.f / l[i];
        size_t rbase = (size_t)(b * TT + q0 + ty * 4 + i) * DD + h * 64 + tx * 4;
#pragma unroll
        for (int j = 0; j < 4; j++)
            ctx[rbase + j] = O[i][j] * inv;
    }
}

// ---------------- launcher ----------------
extern "C" void kernel_launch(void* const* d_in, const int* in_sizes, int n_in,
                              void* d_out, int out_size) {
    const float* x     = (const float*)d_in[0];
    // d_in[1] = mask (causal tril) — implied by attention kernel
    const float* ln1_g = (const float*)d_in[2];
    const float* ln1_b = (const float*)d_in[3];
    const float* Wq    = (const float*)d_in[4];
    const float* bq    = (const float*)d_in[5];
    const float* Wk    = (const float*)d_in[6];
    const float* bk    = (const float*)d_in[7];
    const float* Wv    = (const float*)d_in[8];
    const float* bv    = (const float*)d_in[9];
    const float* Wo    = (const float*)d_in[10];
    const float* bo    = (const float*)d_in[11];
    const float* ln2_g = (const float*)d_in[12];
    const float* ln2_b = (const float*)d_in[13];
    const float* W1    = (const float*)d_in[14];
    const float* b1    = (const float*)d_in[15];
    const float* W2    = (const float*)d_in[16];
    const float* b2    = (const float*)d_in[17];
    float* out = (float*)d_out;

    float* scratch = nullptr;
    cudaGetSymbolAddress((void**)&scratch, d_scratch);
    float* s_h    = scratch + OFF_H;
    float* s_qkv  = scratch + OFF_QKV;
    float* s_ctx  = scratch + OFF_CTX;
    float* s_x1   = scratch + OFF_X1;
    float* s_h2   = scratch + OFF_H2;
    float* s_ff   = scratch + OFF_FF;
    float* s_Wqkv = scratch + OFF_WQKV;
    float* s_bqkv = scratch + OFF_BQKV;

    cudaFuncSetAttribute(attn_kernel, cudaFuncAttributeMaxDynamicSharedMemorySize, ATTN_SMEM);

    // 1. pack QKV weights + bias
    pack_qkv_kernel<<<(DD * 3 * DD + 255) / 256, 256>>>(Wq, Wk, Wv, bq, bk, bv, s_Wqkv, s_bqkv);
    // 2. LN1
    layernorm_kernel<<<MM, 256>>>(x, ln1_g, ln1_b, s_h);
    // 3. QKV projection: [8192,1024] x [1024,3072]
    sgemm_kernel<0><<<dim3(3 * DD / 128, MM / 128), 256>>>(s_h, s_Wqkv, s_bqkv, nullptr,
                                                           s_qkv, MM, 3 * DD, DD);
    // 4. causal flash attention
    attn_kernel<<<dim3(TT / 64, HH, BB), 256, ATTN_SMEM>>>(s_qkv, s_ctx);
    // 5. output projection + residual: x1 = x + ctx*Wo + bo
    sgemm_kernel<1><<<dim3(DD / 128, MM / 128), 256>>>(s_ctx, Wo, bo, x, s_x1, MM, DD, DD);
    // 6. LN2
    layernorm_kernel<<<MM, 256>>>(s_x1, ln2_g, ln2_b, s_h2);
    // 7. FFN up + GELU: [8192,1024] x [1024,4096]
    sgemm_kernel<2><<<dim3(FF / 128, MM / 128), 256>>>(s_h2, W1, b1, nullptr, s_ff, MM, FF, DD);
    // 8. FFN down + residual: out = x1 + ff*W2 + b2
    sgemm_kernel<1><<<dim3(DD / 128, MM / 128), 256>>>(s_ff, W2, b2, s_x1, out, MM, DD, FF);
}

// round 3
// speedup vs baseline: 2.4367x; 2.4367x over previous
#include <cuda_runtime.h>
#include <cuda_bf16.h>
#include <cstdint>
#include <math.h>

// ---------------- problem constants ----------------
#define BB 4
#define TT 2048
#define DD 1024
#define HH 16
#define HD 64
#define FF 4096
#define MM (BB*TT)          // 8192 rows

// ---------------- scratch arena (floats) ----------------
#define OFF_H     0                     // [MM,DD]
#define OFF_QKV   8388608               // [MM,3DD]
#define OFF_CTX   33554432              // [MM,DD]
#define OFF_X1    41943040              // [MM,DD]
#define OFF_H2    50331648              // [MM,DD]
#define OFF_FF    58720256              // [MM,FF]
#define OFF_WQKV  92274688              // [3DD,DD]  transposed+rounded
#define OFF_BQKV  95420416              // [3DD]
#define OFF_WO    95423488              // [DD,DD]   transposed+rounded
#define OFF_W1    96472064              // [FF,DD]   transposed+rounded
#define OFF_W2    100666368             // [DD,FF]   transposed+rounded
#define SCRATCH_TOTAL 104860672

__device__ float d_scratch[SCRATCH_TOTAL];

// ---------------- small helpers ----------------
__device__ __forceinline__ uint32_t smem_u32(const void* p) {
    uint32_t a;
    asm("{ .reg .u64 t; cvta.to.shared.u64 t, %1; cvt.u32.u64 %0, t; }" : "=r"(a) : "l"(p));
    return a;
}
__device__ __forceinline__ float rna_tf32(float x) {
    float r;
    asm("cvt.rna.tf32.f32 %0, %1;" : "=f"(r) : "f"(x));
    return r;
}
__device__ __forceinline__ void cpasync16(uint32_t saddr, const void* g) {
    asm volatile("cp.async.cg.shared.global [%0], [%1], 16;" :: "r"(saddr), "l"(g));
}
__device__ __forceinline__ void ldsm_x4(uint32_t* r, uint32_t addr) {
    asm volatile("ldmatrix.sync.aligned.m8n8.x4.shared.b16 {%0,%1,%2,%3}, [%4];"
                 : "=r"(r[0]), "=r"(r[1]), "=r"(r[2]), "=r"(r[3]) : "r"(addr));
}
__device__ __forceinline__ void mma_tf32(float* d, const uint32_t* a, uint32_t b0, uint32_t b1) {
    asm volatile("mma.sync.aligned.m16n8k8.row.col.f32.tf32.tf32.f32 "
                 "{%0,%1,%2,%3}, {%4,%5,%6,%7}, {%8,%9}, {%0,%1,%2,%3};"
                 : "+f"(d[0]), "+f"(d[1]), "+f"(d[2]), "+f"(d[3])
                 : "r"(a[0]), "r"(a[1]), "r"(a[2]), "r"(a[3]), "r"(b0), "r"(b1));
}
#define SWZ128(o) ((o) ^ (((o) >> 3) & 0x70))

// ---------------- weight transpose + tf32 round: out[c*R+r] = rna(in[r*C+c]) ----------------
__global__ __launch_bounds__(256)
void transpose_round(const float* __restrict__ in, float* __restrict__ out, int R, int C) {
    __shared__ float t[32][33];
    int c0 = blockIdx.x * 32, r0 = blockIdx.y * 32;
#pragma unroll
    for (int i = threadIdx.y; i < 32; i += 8)
        t[i][threadIdx.x] = in[(size_t)(r0 + i) * C + c0 + threadIdx.x];
    __syncthreads();
#pragma unroll
    for (int i = threadIdx.y; i < 32; i += 8)
        out[(size_t)(c0 + i) * R + r0 + threadIdx.x] = rna_tf32(t[threadIdx.x][i]);
}

// ---------------- QKV weight pack: [H,D,HD]x3 -> WqkvT[3D rows(N), D cols(K)] ----------------
__global__ __launch_bounds__(256)
void pack_qkvT(const float* __restrict__ Wq, const float* __restrict__ Wk,
               const float* __restrict__ Wv, float* __restrict__ WqkvT) {
    __shared__ float t[32][33];
    int n0 = blockIdx.y * 32;
    int d0 = blockIdx.x * 32;
    int proj = n0 >> 10;
    int h = (n0 & 1023) >> 6;
    int kk0 = n0 & 63;
    const float* W = (proj == 0) ? Wq : ((proj == 1) ? Wk : Wv);
    const float* base = W + (size_t)h * DD * HD;   // [D, 64]
#pragma unroll
    for (int i = threadIdx.y; i < 32; i += 8)
        t[i][threadIdx.x] = base[(size_t)(d0 + i) * HD + kk0 + threadIdx.x];
    __syncthreads();
#pragma unroll
    for (int i = threadIdx.y; i < 32; i += 8)
        WqkvT[(size_t)(n0 + i) * DD + d0 + threadIdx.x] = rna_tf32(t[threadIdx.x][i]);
}

__global__ void pack_bias(const float* __restrict__ bq, const float* __restrict__ bk,
                          const float* __restrict__ bv, float* __restrict__ bqkv) {
    int n = blockIdx.x * 256 + threadIdx.x;
    if (n >= 3 * DD) return;
    const float* b = (n < DD) ? bq : ((n < 2 * DD) ? bk : bv);
    bqkv[n] = b[n & 1023];
}

// ---------------- LayerNorm (round output to tf32) ----------------
template <bool RND>
__global__ __launch_bounds__(256)
void layernorm_kernel(const float* __restrict__ x, const float* __restrict__ g,
                      const float* __restrict__ bta, float* __restrict__ out) {
    __shared__ float red[16];
    int row = blockIdx.x;
    const float* xr = x + (size_t)row * DD;
    float v[4];
    float s = 0.f, s2 = 0.f;
#pragma unroll
    for (int i = 0; i < 4; i++) {
        v[i] = xr[threadIdx.x + i * 256];
        s += v[i];
        s2 += v[i] * v[i];
    }
#pragma unroll
    for (int o = 16; o > 0; o >>= 1) {
        s  += __shfl_xor_sync(0xffffffffu, s,  o);
        s2 += __shfl_xor_sync(0xffffffffu, s2, o);
    }
    int w = threadIdx.x >> 5;
    if ((threadIdx.x & 31) == 0) { red[w] = s; red[w + 8] = s2; }
    __syncthreads();
    s = 0.f; s2 = 0.f;
#pragma unroll
    for (int i = 0; i < 8; i++) { s += red[i]; s2 += red[i + 8]; }
    float mu  = s * (1.f / (float)DD);
    float var = s2 * (1.f / (float)DD) - mu * mu;
    float inv = rsqrtf(var + 1e-5f);
#pragma unroll
    for (int i = 0; i < 4; i++) {
        int c = threadIdx.x + i * 256;
        float o = (v[i] - mu) * inv * g[c] + bta[c];
        out[(size_t)row * DD + c] = RND ? rna_tf32(o) : o;
    }
}

// ---------------- mma.sync tf32 GEMM: C[M,N] = A[M,K] * BT[N,K]^T ----------------
// BM=128, BN=128, BK=32, 256 threads (8 warps 2x4), warp tile 64x32.
// 3-stage cp.async pipeline, SW128 swizzled K-major smem, ldmatrix fragments.
// EPI: 0 = +bias ; 1 = +bias+res ; 2 = +bias, GELU(exact), round tf32
#define GSTAGES 3
#define GBM 128
#define GBN 128
#define GBK 32
#define A_ST_BYTES (GBM * GBK * 4)       // 16384
#define B_ST_BYTES (GBN * GBK * 4)       // 16384
#define GEMM_SMEM (GSTAGES * (A_ST_BYTES + B_ST_BYTES))   // 98304

template <int EPI>
__global__ __launch_bounds__(256, 2)
void tc_gemm(const float* __restrict__ A, const float* __restrict__ BT,
             const float* __restrict__ bias, const float* __restrict__ res,
             float* __restrict__ C, int M, int N, int K) {
    extern __shared__ __align__(128) char smem[];
    uint32_t sb = smem_u32(smem);
    const uint32_t sA0 = sb;
    const uint32_t sB0 = sb + GSTAGES * A_ST_BYTES;

    int tid = threadIdx.x;
    int lane = tid & 31;
    int warp = tid >> 5;
    int wm = warp >> 2;         // 0..1
    int wn = warp & 3;          // 0..3
    int bm = blockIdx.y * GBM, bn = blockIdx.x * GBN;

    // ldmatrix lane geometry
    int rowin = lane & 7;
    int quad  = lane >> 3;
    int lrow  = (quad & 1) * 8 + rowin;      // row within 16-row tile
    int lkoff = (quad >> 1) * 16;            // byte offset within 32B k-row

    float acc[16][4];
#pragma unroll
    for (int i = 0; i < 16; i++)
#pragma unroll
        for (int j = 0; j < 4; j++) acc[i][j] = 0.f;

    const int NC = K / GBK;

    // per-thread cp.async mapping: 4 chunks of 16B for A, 4 for B
    auto load_chunk = [&](int c) {
        int s = c % GSTAGES;
        uint32_t sA = sA0 + s * A_ST_BYTES;
        uint32_t sB = sB0 + s * B_ST_BYTES;
        const float* Ab = A + (size_t)bm * K + c * GBK;
        const float* Bb = BT + (size_t)bn * K + c * GBK;
#pragma unroll
        for (int i = 0; i < 4; i++) {
            int idx = tid + i * 256;
            int r = idx >> 3, q = idx & 7;
            uint32_t off = (uint32_t)(r * 128 + q * 16);
            cpasync16(sA + SWZ128(off), Ab + (size_t)r * K + q * 4);
        }
#pragma unroll
        for (int i = 0; i < 4; i++) {
            int idx = tid + i * 256;
            int r = idx >> 3, q = idx & 7;
            uint32_t off = (uint32_t)(r * 128 + q * 16);
            cpasync16(sB + SWZ128(off), Bb + (size_t)r * K + q * 4);
        }
        asm volatile("cp.async.commit_group;" ::: "memory");
    };

    load_chunk(0);
    load_chunk(1);

    for (int c = 0; c < NC; c++) {
        if (c + 2 < NC) load_chunk(c + 2);
        int pend = NC - 1 - c;
        if (pend >= 2)      asm volatile("cp.async.wait_group 2;" ::: "memory");
        else if (pend == 1) asm volatile("cp.async.wait_group 1;" ::: "memory");
        else                asm volatile("cp.async.wait_group 0;" ::: "memory");
        __syncthreads();

        int s = c % GSTAGES;
        uint32_t aT = sA0 + s * A_ST_BYTES;
        uint32_t bT = sB0 + s * B_ST_BYTES;
#pragma unroll
        for (int ks = 0; ks < 4; ks++) {
            uint32_t af[4][4];
#pragma unroll
            for (int mi = 0; mi < 4; mi++) {
                uint32_t off = (uint32_t)((wm * 64 + mi * 16 + lrow) * 128 + lkoff + ks * 32);
                ldsm_x4(af[mi], aT + SWZ128(off));
            }
            uint32_t bf[2][4];
#pragma unroll
            for (int np = 0; np < 2; np++) {
                uint32_t off = (uint32_t)((wn * 32 + np * 16 + lrow) * 128 + lkoff + ks * 32);
                ldsm_x4(bf[np], bT + SWZ128(off));
            }
#pragma unroll
            for (int mi = 0; mi < 4; mi++)
#pragma unroll
                for (int ni = 0; ni < 4; ni++) {
                    int np = ni >> 1, sub = ni & 1;
                    mma_tf32(acc[mi * 4 + ni], af[mi], bf[np][sub], bf[np][sub + 2]);
                }
        }
        __syncthreads();
    }

    // epilogue: c-frag layout: c0/c1 at (row=lane>>2, col=2*(lane&3)(+1)); c2/c3 row+8
#pragma unroll
    for (int mi = 0; mi < 4; mi++) {
        int r0 = bm + wm * 64 + mi * 16 + (lane >> 2);
#pragma unroll
        for (int ni = 0; ni < 4; ni++) {
            int col = bn + wn * 32 + ni * 8 + 2 * (lane & 3);
            float2 bb = *(const float2*)(bias + col);
#pragma unroll
            for (int half = 0; half < 2; half++) {
                int r = r0 + half * 8;
                float v0 = acc[mi * 4 + ni][half * 2 + 0] + bb.x;
                float v1 = acc[mi * 4 + ni][half * 2 + 1] + bb.y;
                if (EPI == 1) {
                    float2 rr = *(const float2*)(res + (size_t)r * N + col);
                    v0 += rr.x; v1 += rr.y;
                }
                if (EPI == 2) {
                    v0 = rna_tf32(0.5f * v0 * (1.0f + erff(v0 * 0.70710678118654752f)));
                    v1 = rna_tf32(0.5f * v1 * (1.0f + erff(v1 * 0.70710678118654752f)));
                }
                float2 o; o.x = v0; o.y = v1;
                *(float2*)(C + (size_t)r * N + col) = o;
            }
        }
    }
}

// ---------------- Flash attention (causal), fp32; output tf32-rounded ----------------
#define ATTN_SMEM (4 * 64 * 65 * 4)

__global__ __launch_bounds__(256)
void attn_kernel(const float* __restrict__ qkv, float* __restrict__ ctx) {
    extern __shared__ float sm[];
    float (*Qs)[65] = (float(*)[65])(sm);
    float (*Ks)[65] = (float(*)[65])(sm + 64 * 65);
    float (*Vs)[65] = (float(*)[65])(sm + 2 * 64 * 65);
    float (*Ps)[65] = (float(*)[65])(sm + 3 * 64 * 65);

    int qt = blockIdx.x, h = blockIdx.y, b = blockIdx.z;
    int tid = threadIdx.x;
    int tx = tid & 15, ty = tid >> 4;
    int q0 = qt * 64;

#pragma unroll
    for (int i = 0; i < 4; i++) {
        int l = tid + i * 256;
        int r = l >> 4;
        int c4 = (l & 15) * 4;
        float4 v = *(const float4*)(qkv + (size_t)(b * TT + q0 + r) * 3072 + h * 64 + c4);
        Qs[r][c4 + 0] = v.x * 0.125f;
        Qs[r][c4 + 1] = v.y * 0.125f;
        Qs[r][c4 + 2] = v.z * 0.125f;
        Qs[r][c4 + 3] = v.w * 0.125f;
    }

    float m[4], l[4], O[4][4];
#pragma unroll
    for (int i = 0; i < 4; i++) {
        m[i] = -1e30f; l[i] = 0.f;
#pragma unroll
        for (int j = 0; j < 4; j++) O[i][j] = 0.f;
    }

    for (int jt = 0; jt <= qt; jt++) {
        int kv0 = jt * 64;
        __syncthreads();
#pragma unroll
        for (int i = 0; i < 4; i++) {
            int li = tid + i * 256;
            int r = li >> 4;
            int c4 = (li & 15) * 4;
            const float* base = qkv + (size_t)(b * TT + kv0 + r) * 3072 + h * 64;
            float4 kv4 = *(const float4*)(base + 1024 + c4);
            Ks[r][c4 + 0] = kv4.x; Ks[r][c4 + 1] = kv4.y;
            Ks[r][c4 + 2] = kv4.z; Ks[r][c4 + 3] = kv4.w;
            float4 vv4 = *(const float4*)(base + 2048 + c4);
            Vs[r][c4 + 0] = vv4.x; Vs[r][c4 + 1] = vv4.y;
            Vs[r][c4 + 2] = vv4.z; Vs[r][c4 + 3] = vv4.w;
        }
        __syncthreads();

        float s[4][4];
#pragma unroll
        for (int i = 0; i < 4; i++)
#pragma unroll
            for (int j = 0; j < 4; j++) s[i][j] = 0.f;
#pragma unroll 8
        for (int k = 0; k < 64; k++) {
            float a[4], bb[4];
#pragma unroll
            for (int i = 0; i < 4; i++) a[i] = Qs[ty * 4 + i][k];
#pragma unroll
            for (int j = 0; j < 4; j++) bb[j] = Ks[tx * 4 + j][k];
#pragma unroll
            for (int i = 0; i < 4; i++)
#pragma unroll
                for (int j = 0; j < 4; j++)
                    s[i][j] = fmaf(a[i], bb[j], s[i][j]);
        }

        if (jt == qt) {
#pragma unroll
            for (int i = 0; i < 4; i++)
#pragma unroll
                for (int j = 0; j < 4; j++)
                    if (kv0 + tx * 4 + j > q0 + ty * 4 + i) s[i][j] = -1e30f;
        }

#pragma unroll
        for (int i = 0; i < 4; i++) {
            float mx = s[i][0];
#pragma unroll
            for (int j = 1; j < 4; j++) mx = fmaxf(mx, s[i][j]);
#pragma unroll
            for (int o = 8; o > 0; o >>= 1)
                mx = fmaxf(mx, __shfl_xor_sync(0xffffffffu, mx, o));
            float mnew = fmaxf(m[i], mx);
            float sc = __expf(m[i] - mnew);
            float sum = 0.f;
#pragma unroll
            for (int j = 0; j < 4; j++) {
                s[i][j] = __expf(s[i][j] - mnew);
                sum += s[i][j];
            }
#pragma unroll
            for (int o = 8; o > 0; o >>= 1)
                sum += __shfl_xor_sync(0xffffffffu, sum, o);
            l[i] = l[i] * sc + sum;
            m[i] = mnew;
#pragma unroll
            for (int j = 0; j < 4; j++) O[i][j] *= sc;
        }

#pragma unroll
        for (int i = 0; i < 4; i++)
#pragma unroll
            for (int j = 0; j < 4; j++)
                Ps[ty * 4 + i][tx * 4 + j] = s[i][j];
        __syncthreads();

#pragma unroll 8
        for (int k = 0; k < 64; k++) {
            float p[4], vv[4];
#pragma unroll
            for (int i = 0; i < 4; i++) p[i] = Ps[ty * 4 + i][k];
#pragma unroll
            for (int j = 0; j < 4; j++) vv[j] = Vs[k][tx * 4 + j];
#pragma unroll
            for (int i = 0; i < 4; i++)
#pragma unroll
                for (int j = 0; j < 4; j++)
                    O[i][j] = fmaf(p[i], vv[j], O[i][j]);
        }
    }

#pragma unroll
    for (int i = 0; i < 4; i++) {
        float inv = 1.f / l[i];
        size_t rbase = (size_t)(b * TT + q0 + ty * 4 + i) * DD + h * 64 + tx * 4;
#pragma unroll
        for (int j = 0; j < 4; j++)
            ctx[rbase + j] = rna_tf32(O[i][j] * inv);   // feeds tf32 GEMM
    }
}

// ---------------- launcher ----------------
extern "C" void kernel_launch(void* const* d_in, const int* in_sizes, int n_in,
                              void* d_out, int out_size) {
    const float* x     = (const float*)d_in[0];
    const float* ln1_g = (const float*)d_in[2];
    const float* ln1_b = (const float*)d_in[3];
    const float* Wq    = (const float*)d_in[4];
    const float* bq    = (const float*)d_in[5];
    const float* Wk    = (const float*)d_in[6];
    const float* bk    = (const float*)d_in[7];
    const float* Wv    = (const float*)d_in[8];
    const float* bv    = (const float*)d_in[9];
    const float* Wo    = (const float*)d_in[10];
    const float* bo    = (const float*)d_in[11];
    const float* ln2_g = (const float*)d_in[12];
    const float* ln2_b = (const float*)d_in[13];
    const float* W1    = (const float*)d_in[14];
    const float* b1    = (const float*)d_in[15];
    const float* W2    = (const float*)d_in[16];
    const float* b2    = (const float*)d_in[17];
    float* out = (float*)d_out;

    float* scratch = nullptr;
    cudaGetSymbolAddress((void**)&scratch, d_scratch);
    float* s_h    = scratch + OFF_H;
    float* s_qkv  = scratch + OFF_QKV;
    float* s_ctx  = scratch + OFF_CTX;
    float* s_x1   = scratch + OFF_X1;
    float* s_h2   = scratch + OFF_H2;
    float* s_ff   = scratch + OFF_FF;
    float* s_Wqkv = scratch + OFF_WQKV;
    float* s_bqkv = scratch + OFF_BQKV;
    float* s_Wo   = scratch + OFF_WO;
    float* s_W1   = scratch + OFF_W1;
    float* s_W2   = scratch + OFF_W2;

    cudaFuncSetAttribute(attn_kernel, cudaFuncAttributeMaxDynamicSharedMemorySize, ATTN_SMEM);
    cudaFuncSetAttribute(tc_gemm<0>, cudaFuncAttributeMaxDynamicSharedMemorySize, GEMM_SMEM);
    cudaFuncSetAttribute(tc_gemm<1>, cudaFuncAttributeMaxDynamicSharedMemorySize, GEMM_SMEM);
    cudaFuncSetAttribute(tc_gemm<2>, cudaFuncAttributeMaxDynamicSharedMemorySize, GEMM_SMEM);

    dim3 tb(32, 8);
    // weight prep (transpose + tf32 round)
    pack_qkvT<<<dim3(DD / 32, 3 * DD / 32), tb>>>(Wq, Wk, Wv, s_Wqkv);
    pack_bias<<<(3 * DD + 255) / 256, 256>>>(bq, bk, bv, s_bqkv);
    transpose_round<<<dim3(DD / 32, DD / 32), tb>>>(Wo, s_Wo, DD, DD);
    transpose_round<<<dim3(FF / 32, DD / 32), tb>>>(W1, s_W1, DD, FF);
    transpose_round<<<dim3(DD / 32, FF / 32), tb>>>(W2, s_W2, FF, DD);

    // LN1 (tf32-rounded output)
    layernorm_kernel<true><<<MM, 256>>>(x, ln1_g, ln1_b, s_h);
    // QKV: [8192,1024] x [1024,3072]
    tc_gemm<0><<<dim3(3 * DD / GBN, MM / GBM), 256, GEMM_SMEM>>>(s_h, s_Wqkv, s_bqkv, nullptr,
                                                                 s_qkv, MM, 3 * DD, DD);
    // attention
    attn_kernel<<<dim3(TT / 64, HH, BB), 256, ATTN_SMEM>>>(s_qkv, s_ctx);
    // x1 = x + ctx*Wo + bo
    tc_gemm<1><<<dim3(DD / GBN, MM / GBM), 256, GEMM_SMEM>>>(s_ctx, s_Wo, bo, x, s_x1, MM, DD, DD);
    // LN2 (tf32-rounded)
    layernorm_kernel<true><<<MM, 256>>>(s_x1, ln2_g, ln2_b, s_h2);
    // ff = gelu(h2*W1 + b1)  (tf32-rounded)
    tc_gemm<2><<<dim3(FF / GBN, MM / GBM), 256, GEMM_SMEM>>>(s_h2, s_W1, b1, nullptr, s_ff, MM, FF, DD);
    // out = x1 + ff*W2 + b2
    tc_gemm<1><<<dim3(DD / GBN, MM / GBM), 256, GEMM_SMEM>>>(s_ff, s_W2, b2, s_x1, out, MM, DD, FF);
}

// round 5
// speedup vs baseline: 7.0147x; 2.8788x over previous
#include <cuda_runtime.h>
#include <cuda_fp16.h>
#include <cstdint>
#include <math.h>

// ---------------- problem constants ----------------
#define BB 4
#define TT 2048
#define DD 1024
#define HH 16
#define HD 64
#define FF 4096
#define MM (BB*TT)          // 8192 rows

// ---------------- scratch arena (float units; half buffers cast in) ----------------
#define OFF_H     0                     // [MM,DD] half
#define OFF_QKV   4194304               // [MM,3DD] half
#define OFF_CTX   16777216              // [MM,DD] half
#define OFF_X1    20971520              // [MM,DD] float
#define OFF_H2    29360128              // [MM,DD] half
#define OFF_FF    33554432              // [MM,FF] half
#define OFF_WQKV  50331648              // [3DD,DD] half (transposed)
#define OFF_BQKV  51904512              // [3DD] float
#define OFF_WO    51907584              // [DD,DD] half (transposed)
#define OFF_W1    52431872              // [FF,DD] half (transposed)
#define OFF_W2    54529024              // [DD,FF] half (transposed)
#define SCRATCH_TOTAL 56626176

__device__ float d_scratch[SCRATCH_TOTAL];

// ---------------- helpers ----------------
__device__ __forceinline__ uint32_t smem_u32(const void* p) {
    uint32_t a;
    asm("{ .reg .u64 t; cvta.to.shared.u64 t, %1; cvt.u32.u64 %0, t; }" : "=r"(a) : "l"(p));
    return a;
}
__device__ __forceinline__ void cpasync16(uint32_t saddr, const void* g) {
    asm volatile("cp.async.cg.shared.global [%0], [%1], 16;" :: "r"(saddr), "l"(g));
}
__device__ __forceinline__ void ldsm_x4(uint32_t* r, uint32_t addr) {
    asm volatile("ldmatrix.sync.aligned.m8n8.x4.shared.b16 {%0,%1,%2,%3}, [%4];"
                 : "=r"(r[0]), "=r"(r[1]), "=r"(r[2]), "=r"(r[3]) : "r"(addr));
}
__device__ __forceinline__ void ldsm_x4_t(uint32_t* r, uint32_t addr) {
    asm volatile("ldmatrix.sync.aligned.m8n8.x4.trans.shared.b16 {%0,%1,%2,%3}, [%4];"
                 : "=r"(r[0]), "=r"(r[1]), "=r"(r[2]), "=r"(r[3]) : "r"(addr));
}
__device__ __forceinline__ void mma_f16(float* d, const uint32_t* a, uint32_t b0, uint32_t b1) {
    asm volatile("mma.sync.aligned.m16n8k16.row.col.f32.f16.f16.f32 "
                 "{%0,%1,%2,%3}, {%4,%5,%6,%7}, {%8,%9}, {%0,%1,%2,%3};"
                 : "+f"(d[0]), "+f"(d[1]), "+f"(d[2]), "+f"(d[3])
                 : "r"(a[0]), "r"(a[1]), "r"(a[2]), "r"(a[3]), "r"(b0), "r"(b1));
}
__device__ __forceinline__ uint32_t f22h2(float a, float b) {
    __half2 h = __floats2half2_rn(a, b);
    return *(uint32_t*)&h;
}
#define SWZ128(o) ((o) ^ (((o) >> 3) & 0x70))

// ---------------- weight transpose to half: out[c*R+r] = h(in[r*C+c]) ----------------
__global__ __launch_bounds__(256)
void transpose_half(const float* __restrict__ in, __half* __restrict__ out, int R, int C) {
    __shared__ float t[32][33];
    int c0 = blockIdx.x * 32, r0 = blockIdx.y * 32;
#pragma unroll
    for (int i = threadIdx.y; i < 32; i += 8)
        t[i][threadIdx.x] = in[(size_t)(r0 + i) * C + c0 + threadIdx.x];
    __syncthreads();
#pragma unroll
    for (int i = threadIdx.y; i < 32; i += 8)
        out[(size_t)(c0 + i) * R + r0 + threadIdx.x] = __float2half_rn(t[threadIdx.x][i]);
}

// ---------------- QKV weight pack: [H,D,HD]x3 -> WqkvT[3D(N), D(K)] half ----------------
__global__ __launch_bounds__(256)
void pack_qkvT(const float* __restrict__ Wq, const float* __restrict__ Wk,
               const float* __restrict__ Wv, __half* __restrict__ WqkvT) {
    __shared__ float t[32][33];
    int n0 = blockIdx.y * 32;
    int d0 = blockIdx.x * 32;
    int proj = n0 >> 10;
    int h = (n0 & 1023) >> 6;
    int kk0 = n0 & 63;
    const float* W = (proj == 0) ? Wq : ((proj == 1) ? Wk : Wv);
    const float* base = W + (size_t)h * DD * HD;
#pragma unroll
    for (int i = threadIdx.y; i < 32; i += 8)
        t[i][threadIdx.x] = base[(size_t)(d0 + i) * HD + kk0 + threadIdx.x];
    __syncthreads();
#pragma unroll
    for (int i = threadIdx.y; i < 32; i += 8)
        WqkvT[(size_t)(n0 + i) * DD + d0 + threadIdx.x] = __float2half_rn(t[threadIdx.x][i]);
}

__global__ void pack_bias(const float* __restrict__ bq, const float* __restrict__ bk,
                          const float* __restrict__ bv, float* __restrict__ bqkv) {
    int n = blockIdx.x * 256 + threadIdx.x;
    if (n >= 3 * DD) return;
    const float* b = (n < DD) ? bq : ((n < 2 * DD) ? bk : bv);
    bqkv[n] = b[n & 1023];
}

// ---------------- LayerNorm: fp32 in, half out ----------------
__global__ __launch_bounds__(256)
void layernorm_kernel(const float* __restrict__ x, const float* __restrict__ g,
                      const float* __restrict__ bta, __half* __restrict__ out) {
    __shared__ float red[16];
    int row = blockIdx.x;
    const float* xr = x + (size_t)row * DD;
    float v[4];
    float s = 0.f, s2 = 0.f;
#pragma unroll
    for (int i = 0; i < 4; i++) {
        v[i] = xr[threadIdx.x + i * 256];
        s += v[i];
        s2 += v[i] * v[i];
    }
#pragma unroll
    for (int o = 16; o > 0; o >>= 1) {
        s  += __shfl_xor_sync(0xffffffffu, s,  o);
        s2 += __shfl_xor_sync(0xffffffffu, s2, o);
    }
    int w = threadIdx.x >> 5;
    if ((threadIdx.x & 31) == 0) { red[w] = s; red[w + 8] = s2; }
    __syncthreads();
    s = 0.f; s2 = 0.f;
#pragma unroll
    for (int i = 0; i < 8; i++) { s += red[i]; s2 += red[i + 8]; }
    float mu  = s * (1.f / (float)DD);
    float var = s2 * (1.f / (float)DD) - mu * mu;
    float inv = rsqrtf(var + 1e-5f);
#pragma unroll
    for (int i = 0; i < 4; i++) {
        int c = threadIdx.x + i * 256;
        out[(size_t)row * DD + c] = __float2half_rn((v[i] - mu) * inv * g[c] + bta[c]);
    }
}

// ---------------- fp16 mma GEMM: C[M,N] = A[M,K] * BT[N,K]^T (fp32 acc) ----------------
// BM=128, BN=128, BK=64 halves (128B rows), 256 threads (8 warps 2x4), warp 64x32.
// 3-stage cp.async pipeline, SW128 smem, ldmatrix fragments.
// EPI: 0 = +bias -> half ; 1 = +bias+res(f32) -> f32 ; 2 = +bias, GELU -> half
#define GSTAGES 3
#define GBM 128
#define GBN 128
#define GBK 64
#define A_ST_BYTES (GBM * 128)           // 16384
#define B_ST_BYTES (GBN * 128)           // 16384
#define GEMM_SMEM (GSTAGES * (A_ST_BYTES + B_ST_BYTES))   // 98304

template <int EPI>
__global__ __launch_bounds__(256, 2)
void tc_gemm(const __half* __restrict__ A, const __half* __restrict__ BT,
             const float* __restrict__ bias, const float* __restrict__ res,
             void* __restrict__ Cout, int M, int N, int K) {
    extern __shared__ __align__(128) char smem[];
    uint32_t sb = smem_u32(smem);
    const uint32_t sA0 = sb;
    const uint32_t sB0 = sb + GSTAGES * A_ST_BYTES;

    int tid = threadIdx.x;
    int lane = tid & 31;
    int warp = tid >> 5;
    int wm = warp >> 2;
    int wn = warp & 3;
    int bm = blockIdx.y * GBM, bn = blockIdx.x * GBN;

    int rowin = lane & 7;
    int quad  = lane >> 3;
    int lrow  = (quad & 1) * 8 + rowin;
    int lkoff = (quad >> 1) * 16;

    float acc[16][4];
#pragma unroll
    for (int i = 0; i < 16; i++)
#pragma unroll
        for (int j = 0; j < 4; j++) acc[i][j] = 0.f;

    const int NC = K / GBK;

    auto load_chunk = [&](int c) {
        int s = c % GSTAGES;
        uint32_t sA = sA0 + s * A_ST_BYTES;
        uint32_t sB = sB0 + s * B_ST_BYTES;
        const __half* Ab = A + (size_t)bm * K + c * GBK;
        const __half* Bb = BT + (size_t)bn * K + c * GBK;
#pragma unroll
        for (int i = 0; i < 4; i++) {
            int idx = tid + i * 256;
            int r = idx >> 3, q = idx & 7;
            cpasync16(sA + SWZ128((uint32_t)(r * 128 + q * 16)), Ab + (size_t)r * K + q * 8);
        }
#pragma unroll
        for (int i = 0; i < 4; i++) {
            int idx = tid + i * 256;
            int r = idx >> 3, q = idx & 7;
            cpasync16(sB + SWZ128((uint32_t)(r * 128 + q * 16)), Bb + (size_t)r * K + q * 8);
        }
        asm volatile("cp.async.commit_group;" ::: "memory");
    };

    load_chunk(0);
    load_chunk(1);

    for (int c = 0; c < NC; c++) {
        if (c + 2 < NC) load_chunk(c + 2);
        int pend = NC - 1 - c;
        if (pend >= 2)      asm volatile("cp.async.wait_group 2;" ::: "memory");
        else if (pend == 1) asm volatile("cp.async.wait_group 1;" ::: "memory");
        else                asm volatile("cp.async.wait_group 0;" ::: "memory");
        __syncthreads();

        int s = c % GSTAGES;
        uint32_t aT = sA0 + s * A_ST_BYTES;
        uint32_t bT = sB0 + s * B_ST_BYTES;
#pragma unroll
        for (int ks = 0; ks < 4; ks++) {            // k16 steps within BK=64
            uint32_t af[4][4];
#pragma unroll
            for (int mi = 0; mi < 4; mi++) {
                uint32_t off = (uint32_t)((wm * 64 + mi * 16 + lrow) * 128 + lkoff + ks * 32);
                ldsm_x4(af[mi], aT + SWZ128(off));
            }
            uint32_t bf[2][4];
#pragma unroll
            for (int np = 0; np < 2; np++) {
                uint32_t off = (uint32_t)((wn * 32 + np * 16 + lrow) * 128 + lkoff + ks * 32);
                ldsm_x4(bf[np], bT + SWZ128(off));
            }
#pragma unroll
            for (int mi = 0; mi < 4; mi++)
#pragma unroll
                for (int ni = 0; ni < 4; ni++) {
                    int np = ni >> 1, sub = ni & 1;
                    mma_f16(acc[mi * 4 + ni], af[mi], bf[np][sub], bf[np][sub + 2]);
                }
        }
        __syncthreads();
    }

    // epilogue: c0/c1 at (g, 2t/2t+1); c2/c3 at (g+8, ...)
#pragma unroll
    for (int mi = 0; mi < 4; mi++) {
        int r0 = bm + wm * 64 + mi * 16 + (lane >> 2);
#pragma unroll
        for (int ni = 0; ni < 4; ni++) {
            int col = bn + wn * 32 + ni * 8 + 2 * (lane & 3);
            float2 bb = *(const float2*)(bias + col);
#pragma unroll
            for (int half_ = 0; half_ < 2; half_++) {
                int r = r0 + half_ * 8;
                float v0 = acc[mi * 4 + ni][half_ * 2 + 0] + bb.x;
                float v1 = acc[mi * 4 + ni][half_ * 2 + 1] + bb.y;
                if (EPI == 1) {
                    float2 rr = *(const float2*)(res + (size_t)r * N + col);
                    v0 += rr.x; v1 += rr.y;
                    *(float2*)((float*)Cout + (size_t)r * N + col) = make_float2(v0, v1);
                } else if (EPI == 2) {
                    v0 = 0.5f * v0 * (1.0f + erff(v0 * 0.70710678118654752f));
                    v1 = 0.5f * v1 * (1.0f + erff(v1 * 0.70710678118654752f));
                    *(uint32_t*)((__half*)Cout + (size_t)r * N + col) = f22h2(v0, v1);
                } else {
                    *(uint32_t*)((__half*)Cout + (size_t)r * N + col) = f22h2(v0, v1);
                }
            }
        }
    }
}

// ---------------- Flash attention (causal), fp16 mma, fp32 softmax ----------------
// grid (T/64, H, B), 128 threads (4 warps; warp owns 16 q rows).
// smem: Q 8KB | K/V double-buffered 2x16KB => 40KB.
#define ATTN_SMEM (8192 + 2 * 16384)
#define SQ_OFF 0
#define SK_OFF(s) (8192 + (s) * 16384)
#define SV_OFF(s) (16384 + (s) * 16384)

__global__ __launch_bounds__(128)
void attn_kernel(const __half* __restrict__ qkv, __half* __restrict__ ctx) {
    extern __shared__ __align__(128) char smem[];
    uint32_t sb = smem_u32(smem);

    int qt = blockIdx.x, h = blockIdx.y, b = blockIdx.z;
    int tid = threadIdx.x;
    int lane = tid & 31;
    int warp = tid >> 5;
    int q0 = qt * 64;

    int rowin = lane & 7;
    int quad  = lane >> 3;
    int lrow  = (quad & 1) * 8 + rowin;
    int lkoff = (quad >> 1) * 16;
    int g = lane >> 2;          // row within m16
    int t2 = 2 * (lane & 3);    // col pair base

    // ---- prologue loads: Q tile + KV(0) ----
    const __half* qbase = qkv + (size_t)(b * TT + q0) * 3072 + h * 64;
#pragma unroll
    for (int i = 0; i < 4; i++) {
        int idx = tid + i * 128;
        int r = idx >> 3, q = idx & 7;
        cpasync16(sb + SQ_OFF + SWZ128((uint32_t)(r * 128 + q * 16)),
                  qbase + (size_t)r * 3072 + q * 8);
    }
    auto load_kv = [&](int jt) {
        int s = jt & 1;
        const __half* kb = qkv + (size_t)(b * TT + jt * 64) * 3072 + 1024 + h * 64;
        const __half* vb = kb + 1024;
#pragma unroll
        for (int i = 0; i < 4; i++) {
            int idx = tid + i * 128;
            int r = idx >> 3, q = idx & 7;
            uint32_t off = SWZ128((uint32_t)(r * 128 + q * 16));
            cpasync16(sb + SK_OFF(s) + off, kb + (size_t)r * 3072 + q * 8);
            cpasync16(sb + SV_OFF(s) + off, vb + (size_t)r * 3072 + q * 8);
        }
        asm volatile("cp.async.commit_group;" ::: "memory");
    };
    load_kv(0);   // group also contains Q loads

    float m0 = -1e30f, m1 = -1e30f, l0 = 0.f, l1 = 0.f;
    float accO[8][4];
#pragma unroll
    for (int i = 0; i < 8; i++)
#pragma unroll
        for (int j = 0; j < 4; j++) accO[i][j] = 0.f;

    uint32_t qaf[4][4];
    bool qloaded = false;

    for (int jt = 0; jt <= qt; jt++) {
        if (jt + 1 <= qt) load_kv(jt + 1);
        if (jt + 1 <= qt) asm volatile("cp.async.wait_group 1;" ::: "memory");
        else              asm volatile("cp.async.wait_group 0;" ::: "memory");
        __syncthreads();

        int s = jt & 1;
        uint32_t kT = sb + SK_OFF(s);
        uint32_t vT = sb + SV_OFF(s);

        if (!qloaded) {
            qloaded = true;
#pragma unroll
            for (int ks = 0; ks < 4; ks++) {
                uint32_t off = (uint32_t)((warp * 16 + lrow) * 128 + lkoff + ks * 32);
                ldsm_x4(qaf[ks], sb + SQ_OFF + SWZ128(off));
            }
        }

        // ---- S = Q K^T ----
        float sc[8][4];
#pragma unroll
        for (int i = 0; i < 8; i++)
#pragma unroll
            for (int j = 0; j < 4; j++) sc[i][j] = 0.f;
#pragma unroll
        for (int ks = 0; ks < 4; ks++) {
#pragma unroll
            for (int np = 0; np < 4; np++) {
                uint32_t bf[4];
                uint32_t off = (uint32_t)((np * 16 + lrow) * 128 + lkoff + ks * 32);
                ldsm_x4(bf, kT + SWZ128(off));
                mma_f16(sc[np * 2 + 0], qaf[ks], bf[0], bf[2]);
                mma_f16(sc[np * 2 + 1], qaf[ks], bf[1], bf[3]);
            }
        }

        // scale + causal mask
#pragma unroll
        for (int i = 0; i < 8; i++)
#pragma unroll
            for (int j = 0; j < 4; j++) sc[i][j] *= 0.125f;
        if (jt == qt) {
            int r0 = warp * 16 + g, r1 = r0 + 8;
#pragma unroll
            for (int i = 0; i < 8; i++) {
                int c0 = i * 8 + t2;
                if (c0     > r0) sc[i][0] = -1e30f;
                if (c0 + 1 > r0) sc[i][1] = -1e30f;
                if (c0     > r1) sc[i][2] = -1e30f;
                if (c0 + 1 > r1) sc[i][3] = -1e30f;
            }
        }

        // ---- online softmax (rows g, g+8) ----
        float mx0 = -1e30f, mx1 = -1e30f;
#pragma unroll
        for (int i = 0; i < 8; i++) {
            mx0 = fmaxf(mx0, fmaxf(sc[i][0], sc[i][1]));
            mx1 = fmaxf(mx1, fmaxf(sc[i][2], sc[i][3]));
        }
#pragma unroll
        for (int o = 1; o <= 2; o <<= 1) {
            mx0 = fmaxf(mx0, __shfl_xor_sync(0xffffffffu, mx0, o));
            mx1 = fmaxf(mx1, __shfl_xor_sync(0xffffffffu, mx1, o));
        }
        float mn0 = fmaxf(m0, mx0), mn1 = fmaxf(m1, mx1);
        float sc0 = __expf(m0 - mn0), sc1 = __expf(m1 - mn1);
        float sum0 = 0.f, sum1 = 0.f;
        uint32_t ph[8][2];
#pragma unroll
        for (int i = 0; i < 8; i++) {
            float p0 = __expf(sc[i][0] - mn0);
            float p1 = __expf(sc[i][1] - mn0);
            float p2 = __expf(sc[i][2] - mn1);
            float p3 = __expf(sc[i][3] - mn1);
            sum0 += p0 + p1; sum1 += p2 + p3;
            ph[i][0] = f22h2(p0, p1);
            ph[i][1] = f22h2(p2, p3);
        }
#pragma unroll
        for (int o = 1; o <= 2; o <<= 1) {
            sum0 += __shfl_xor_sync(0xffffffffu, sum0, o);
            sum1 += __shfl_xor_sync(0xffffffffu, sum1, o);
        }
        l0 = l0 * sc0 + sum0; l1 = l1 * sc1 + sum1;
        m0 = mn0; m1 = mn1;
#pragma unroll
        for (int i = 0; i < 8; i++) {
            accO[i][0] *= sc0; accO[i][1] *= sc0;
            accO[i][2] *= sc1; accO[i][3] *= sc1;
        }

        // ---- O += P V  (P A-frags from registers; V B-frags via ldmatrix.trans) ----
#pragma unroll
        for (int kt = 0; kt < 4; kt++) {
            uint32_t pa[4] = { ph[2 * kt][0], ph[2 * kt][1], ph[2 * kt + 1][0], ph[2 * kt + 1][1] };
#pragma unroll
            for (int dg = 0; dg < 4; dg++) {
                uint32_t bf[4];
                uint32_t off = (uint32_t)((kt * 16 + lrow) * 128 + dg * 32 + lkoff);
                ldsm_x4_t(bf, vT + SWZ128(off));
                mma_f16(accO[dg * 2 + 0], pa, bf[0], bf[1]);
                mma_f16(accO[dg * 2 + 1], pa, bf[2], bf[3]);
            }
        }
        __syncthreads();
    }

    // ---- normalize + write ctx (half) ----
    float inv0 = 1.f / l0, inv1 = 1.f / l1;
    int r0 = b * TT + q0 + warp * 16 + g;
#pragma unroll
    for (int i = 0; i < 8; i++) {
        int col = h * 64 + i * 8 + t2;
        *(uint32_t*)(ctx + (size_t)r0 * DD + col)       = f22h2(accO[i][0] * inv0, accO[i][1] * inv0);
        *(uint32_t*)(ctx + (size_t)(r0 + 8) * DD + col) = f22h2(accO[i][2] * inv1, accO[i][3] * inv1);
    }
}

// ---------------- launcher ----------------
extern "C" void kernel_launch(void* const* d_in, const int* in_sizes, int n_in,
                              void* d_out, int out_size) {
    const float* x     = (const float*)d_in[0];
    const float* ln1_g = (const float*)d_in[2];
    const float* ln1_b = (const float*)d_in[3];
    const float* Wq    = (const float*)d_in[4];
    const float* bq    = (const float*)d_in[5];
    const float* Wk    = (const float*)d_in[6];
    const float* bk    = (const float*)d_in[7];
    const float* Wv    = (const float*)d_in[8];
    const float* bv    = (const float*)d_in[9];
    const float* Wo    = (const float*)d_in[10];
    const float* bo    = (const float*)d_in[11];
    const float* ln2_g = (const float*)d_in[12];
    const float* ln2_b = (const float*)d_in[13];
    const float* W1    = (const float*)d_in[14];
    const float* b1    = (const float*)d_in[15];
    const float* W2    = (const float*)d_in[16];
    const float* b2    = (const float*)d_in[17];
    float* out = (float*)d_out;

    float* scratch = nullptr;
    cudaGetSymbolAddress((void**)&scratch, d_scratch);
    __half* s_h    = (__half*)(scratch + OFF_H);
    __half* s_qkv  = (__half*)(scratch + OFF_QKV);
    __half* s_ctx  = (__half*)(scratch + OFF_CTX);
    float*  s_x1   = scratch + OFF_X1;
    __half* s_h2   = (__half*)(scratch + OFF_H2);
    __half* s_ff   = (__half*)(scratch + OFF_FF);
    __half* s_Wqkv = (__half*)(scratch + OFF_WQKV);
    float*  s_bqkv = scratch + OFF_BQKV;
    __half* s_Wo   = (__half*)(scratch + OFF_WO);
    __half* s_W1   = (__half*)(scratch + OFF_W1);
    __half* s_W2   = (__half*)(scratch + OFF_W2);

    cudaFuncSetAttribute(attn_kernel, cudaFuncAttributeMaxDynamicSharedMemorySize, ATTN_SMEM);
    cudaFuncSetAttribute(tc_gemm<0>, cudaFuncAttributeMaxDynamicSharedMemorySize, GEMM_SMEM);
    cudaFuncSetAttribute(tc_gemm<1>, cudaFuncAttributeMaxDynamicSharedMemorySize, GEMM_SMEM);
    cudaFuncSetAttribute(tc_gemm<2>, cudaFuncAttributeMaxDynamicSharedMemorySize, GEMM_SMEM);

    dim3 tb(32, 8);
    // weight prep (transpose + half round)
    pack_qkvT<<<dim3(DD / 32, 3 * DD / 32), tb>>>(Wq, Wk, Wv, s_Wqkv);
    pack_bias<<<(3 * DD + 255) / 256, 256>>>(bq, bk, bv, s_bqkv);
    transpose_half<<<dim3(DD / 32, DD / 32), tb>>>(Wo, s_Wo, DD, DD);
    transpose_half<<<dim3(FF / 32, DD / 32), tb>>>(W1, s_W1, DD, FF);
    transpose_half<<<dim3(DD / 32, FF / 32), tb>>>(W2, s_W2, FF, DD);

    // LN1 -> half
    layernorm_kernel<<<MM, 256>>>(x, ln1_g, ln1_b, s_h);
    // QKV: [8192,1024] x [1024,3072] -> half
    tc_gemm<0><<<dim3(3 * DD / GBN, MM / GBM), 256, GEMM_SMEM>>>(s_h, s_Wqkv, s_bqkv, nullptr,
                                                                 s_qkv, MM, 3 * DD, DD);
    // attention (fp16 mma)
    attn_kernel<<<dim3(TT / 64, HH, BB), 128, ATTN_SMEM>>>(s_qkv, s_ctx);
    // x1 = x + ctx*Wo + bo  (fp32 out)
    tc_gemm<1><<<dim3(DD / GBN, MM / GBM), 256, GEMM_SMEM>>>(s_ctx, s_Wo, bo, x, s_x1, MM, DD, DD);
    // LN2 -> half
    layernorm_kernel<<<MM, 256>>>(s_x1, ln2_g, ln2_b, s_h2);
    // ff = gelu(h2*W1 + b1) -> half
    tc_gemm<2><<<dim3(FF / GBN, MM / GBM), 256, GEMM_SMEM>>>(s_h2, s_W1, b1, nullptr, s_ff, MM, FF, DD);
    // out = x1 + ff*W2 + b2  (fp32 out)
    tc_gemm<1><<<dim3(DD / GBN, MM / GBM), 256, GEMM_SMEM>>>(s_ff, s_W2, b2, s_x1, out, MM, DD, FF);
}